// round 1
// baseline (speedup 1.0000x reference)
#include <cuda_runtime.h>

#define GEXP 16
#define DDIM 512
#define BMAX 4096
#define MAXTILES (BMAX / 64 + GEXP)

// ---- device scratch (static: no allocations allowed) ----
__device__ int   g_offsets[GEXP + 1];
__device__ int   g_perm[BMAX];
__device__ int   g_tile_expert[MAXTILES];
__device__ int   g_tile_row[MAXTILES];
__device__ int   g_num_tiles;
__device__ float g_h[2][BMAX * DDIM];   // layer-0 hidden, permuted order; [0]=pi, [1]=vf

// ---------------------------------------------------------------------------
// Setup: detect goal dtype (int64 vs int32), histogram, prefix sum, build
// token permutation sorted by expert, and the GEMM tile list.
// Single block so everything is ordered without extra launches.
// ---------------------------------------------------------------------------
__global__ void setup_kernel(const void* __restrict__ goal_raw, int B)
{
    __shared__ int s_cnt[GEXP];
    __shared__ int s_off[GEXP + 1];
    __shared__ int s_fill[GEXP];
    __shared__ int s_is64;

    int t = threadIdx.x;
    if (t < GEXP) { s_cnt[t] = 0; s_fill[t] = 0; }
    if (t == 0) {
        // If the buffer is really int32, interpreting pairs as int64 yields
        // values >= GEXP almost surely (high word is a random goal in [0,16)).
        const long long* p = (const long long*)goal_raw;
        int f = 1;
        int n = (B < 32) ? B : 32;
        for (int i = 0; i < n; i++) {
            long long v = p[i];
            if (v < 0 || v >= GEXP) { f = 0; break; }
        }
        s_is64 = f;
    }
    __syncthreads();
    const int is64 = s_is64;

    for (int i = t; i < B; i += blockDim.x) {
        int g = is64 ? (int)((const long long*)goal_raw)[i]
                     : ((const int*)goal_raw)[i];
        atomicAdd(&s_cnt[g], 1);
    }
    __syncthreads();

    if (t == 0) {
        int acc = 0, nt = 0;
        for (int g = 0; g < GEXP; g++) {
            s_off[g] = acc;
            for (int r = 0; r < s_cnt[g]; r += 64) {
                g_tile_expert[nt] = g;
                g_tile_row[nt]    = acc + r;
                nt++;
            }
            acc += s_cnt[g];
        }
        s_off[GEXP] = acc;
        g_num_tiles = nt;
        for (int g = 0; g <= GEXP; g++) g_offsets[g] = s_off[g];
    }
    __syncthreads();

    for (int i = t; i < B; i += blockDim.x) {
        int g = is64 ? (int)((const long long*)goal_raw)[i]
                     : ((const int*)goal_raw)[i];
        int pos = s_off[g] + atomicAdd(&s_fill[g], 1);
        g_perm[pos] = i;   // order within expert irrelevant: per-token output identical
    }
}

// ---------------------------------------------------------------------------
// One fused "layer" for both branches (blockIdx.z: 0=pi, 1=vf).
// Y[m, n] = tanh( sum_d X[m, d] * W[g, d, n] + bias[g, n] )
// Tile: 64 rows x 64 cols, K-chunk 16. 256 threads, 4x4 register microtile.
// mode bit0: gather input rows through g_perm (layer 0)
// mode bit1: scatter output rows through g_perm (layer 1)
// mode bit2: input is internal scratch g_h[z]
// mode bit3: output is internal scratch g_h[z]
// ---------------------------------------------------------------------------
__global__ __launch_bounds__(256)
void expert_layer(const float* __restrict__ Xext,
                  const float* __restrict__ Wa, const float* __restrict__ Ba,
                  const float* __restrict__ Wb, const float* __restrict__ Bb,
                  float* __restrict__ Ya, float* __restrict__ Yb,
                  int mode)
{
    const int tile = blockIdx.x;
    if (tile >= g_num_tiles) return;

    const int g    = g_tile_expert[tile];
    const int row0 = g_tile_row[tile];
    int rows = g_offsets[g + 1] - row0;
    if (rows > 64) rows = 64;
    const int n0 = blockIdx.y * 64;
    const int z  = blockIdx.z;

    const bool gather_in   = (mode & 1) != 0;
    const bool scatter_out = (mode & 2) != 0;
    const bool in_scratch  = (mode & 4) != 0;
    const bool out_scratch = (mode & 8) != 0;

    const float* X    = in_scratch  ? g_h[z] : Xext;
    float*       Y    = out_scratch ? g_h[z] : (z ? Yb : Ya);
    const float* W    = z ? Wb : Wa;
    const float* bias = z ? Bb : Ba;
    const float* Wg   = W + (size_t)g * DDIM * DDIM;
    const float* biasg = bias + g * DDIM;

    __shared__ float As[16][64];
    __shared__ float Bs[16][64];

    const int tid = threadIdx.x;
    const int tx = tid & 15;          // n microtile
    const int ty = tid >> 4;          // m microtile

    // A-tile loader mapping: each thread loads a float4 along K
    const int am = tid >> 2;          // 0..63 (row within tile)
    const int ak = (tid & 3) * 4;     // 0,4,8,12 (k within chunk)
    const bool avalid = (am < rows);
    const float* Aptr = nullptr;
    if (avalid) {
        int p = row0 + am;
        int arow = gather_in ? g_perm[p] : p;
        Aptr = X + (size_t)arow * DDIM;
    }

    // B-tile loader mapping
    const int bk = tid >> 4;          // 0..15
    const int bn = (tid & 15) * 4;    // 0..60

    float acc[4][4] = {};

    for (int k0 = 0; k0 < DDIM; k0 += 16) {
        float4 av = avalid ? *(const float4*)(Aptr + k0 + ak)
                           : make_float4(0.f, 0.f, 0.f, 0.f);
        float4 bv = *(const float4*)(Wg + (size_t)(k0 + bk) * DDIM + n0 + bn);

        __syncthreads();   // previous compute done before overwrite
        As[ak + 0][am] = av.x;
        As[ak + 1][am] = av.y;
        As[ak + 2][am] = av.z;
        As[ak + 3][am] = av.w;
        *(float4*)&Bs[bk][bn] = bv;
        __syncthreads();

        #pragma unroll
        for (int kk = 0; kk < 16; kk++) {
            float4 ra = *(const float4*)&As[kk][ty * 4];
            float4 rb = *(const float4*)&Bs[kk][tx * 4];
            float a[4] = {ra.x, ra.y, ra.z, ra.w};
            float b[4] = {rb.x, rb.y, rb.z, rb.w};
            #pragma unroll
            for (int i = 0; i < 4; i++)
                #pragma unroll
                for (int j = 0; j < 4; j++)
                    acc[i][j] = fmaf(a[i], b[j], acc[i][j]);
        }
    }

    float4 bz = *(const float4*)(biasg + n0 + tx * 4);
    const float bb4[4] = {bz.x, bz.y, bz.z, bz.w};

    #pragma unroll
    for (int i = 0; i < 4; i++) {
        int m = ty * 4 + i;
        if (m < rows) {
            int p = row0 + m;
            int orow = scatter_out ? g_perm[p] : p;
            float4 o;
            o.x = tanhf(acc[i][0] + bb4[0]);
            o.y = tanhf(acc[i][1] + bb4[1]);
            o.z = tanhf(acc[i][2] + bb4[2]);
            o.w = tanhf(acc[i][3] + bb4[3]);
            *(float4*)(Y + (size_t)orow * DDIM + n0 + tx * 4) = o;
        }
    }
}

// ---------------------------------------------------------------------------
extern "C" void kernel_launch(void* const* d_in, const int* in_sizes, int n_in,
                              void* d_out, int out_size)
{
    const float* features = (const float*)d_in[0];
    const float* Wp0 = (const float*)d_in[1];
    const float* bp0 = (const float*)d_in[2];
    const float* Wp1 = (const float*)d_in[3];
    const float* bp1 = (const float*)d_in[4];
    const float* Wv0 = (const float*)d_in[5];
    const float* bv0 = (const float*)d_in[6];
    const float* Wv1 = (const float*)d_in[7];
    const float* bv1 = (const float*)d_in[8];
    const void*  goal = d_in[9];

    int B = in_sizes[0] / DDIM;
    if (B > BMAX) B = BMAX;

    float* out_pi = (float*)d_out;
    float* out_vf = out_pi + (size_t)B * DDIM;

    setup_kernel<<<1, 1024>>>(goal, B);

    dim3 grid(B / 64 + GEXP, DDIM / 64, 2);
    dim3 block(256);

    // Layer 0: gather input rows via perm (bit0), write internal scratch (bit3)
    expert_layer<<<grid, block>>>(features, Wp0, bp0, Wv0, bv0,
                                  nullptr, nullptr, /*mode=*/1 | 8);

    // Layer 1: read internal scratch (bit2), scatter output rows via perm (bit1)
    expert_layer<<<grid, block>>>(nullptr, Wp1, bp1, Wv1, bv1,
                                  out_pi, out_vf, /*mode=*/2 | 4);
}

// round 5
// speedup vs baseline: 1.2535x; 1.2535x over previous
#include <cuda_runtime.h>
#include <cuda_bf16.h>
#include <mma.h>
#include <cstdint>

using namespace nvcuda;

#define GEXP 16
#define DDIM 512
#define BMAX 4096
#define TILEM 128
#define MAXTILES (BMAX / TILEM + GEXP)
#define LDA 72                       // bf16 elems per smem row (64 + 8 pad)
#define LDS_F32 132                  // f32 staging leading dim
#define SMEM_TOTAL 73728             // 4 x (128*72*2) bytes

// ---------------- device scratch (static; no allocations allowed) ----------
__device__ int g_offsets[GEXP + 1];
__device__ int g_perm[BMAX];
__device__ int g_tile_expert[MAXTILES];
__device__ int g_tile_row[MAXTILES];
__device__ int g_num_tiles;

// transposed bf16 hi/lo weights: [mat][g][h][d], d contiguous
__device__ __nv_bfloat16 g_Wt_hi[4][GEXP * DDIM * DDIM];
__device__ __nv_bfloat16 g_Wt_lo[4][GEXP * DDIM * DDIM];
// features split (original token order)
__device__ __nv_bfloat16 g_A_hi[BMAX * DDIM];
__device__ __nv_bfloat16 g_A_lo[BMAX * DDIM];
// layer-0 hidden split, permuted token order, [branch]
__device__ __nv_bfloat16 g_H_hi[2][BMAX * DDIM];
__device__ __nv_bfloat16 g_H_lo[2][BMAX * DDIM];

// ---------------- helpers ---------------------------------------------------
__device__ __forceinline__ uint32_t smem_u32(const void* p) {
    uint32_t a;
    asm("{ .reg .u64 t; cvta.to.shared.u64 t, %1; cvt.u32.u64 %0, t; }" : "=r"(a) : "l"(p));
    return a;
}

__device__ __forceinline__ void cp16(uint32_t dst, const void* src) {
    size_t gsrc = (size_t)__cvta_generic_to_global(src);
    asm volatile("cp.async.cg.shared.global [%0], [%1], 16;" :: "r"(dst), "l"(gsrc) : "memory");
}

// ---------------------------------------------------------------------------
// Setup: dtype-detect goal, histogram, offsets, permutation, tile list.
// ---------------------------------------------------------------------------
__global__ void setup_kernel(const void* __restrict__ goal_raw, int B)
{
    __shared__ int s_cnt[GEXP];
    __shared__ int s_off[GEXP + 1];
    __shared__ int s_fill[GEXP];
    __shared__ int s_is64;

    int t = threadIdx.x;
    if (t < GEXP) { s_cnt[t] = 0; s_fill[t] = 0; }
    if (t == 0) {
        const long long* p = (const long long*)goal_raw;
        int f = 1;
        int n = (B < 32) ? B : 32;
        for (int i = 0; i < n; i++) {
            long long v = p[i];
            if (v < 0 || v >= GEXP) { f = 0; break; }
        }
        s_is64 = f;
    }
    __syncthreads();
    const int is64 = s_is64;

    for (int i = t; i < B; i += blockDim.x) {
        int g = is64 ? (int)((const long long*)goal_raw)[i]
                     : ((const int*)goal_raw)[i];
        atomicAdd(&s_cnt[g], 1);
    }
    __syncthreads();

    if (t == 0) {
        int acc = 0, nt = 0;
        for (int g = 0; g < GEXP; g++) {
            s_off[g] = acc;
            for (int r = 0; r < s_cnt[g]; r += TILEM) {
                g_tile_expert[nt] = g;
                g_tile_row[nt]    = acc + r;
                nt++;
            }
            acc += s_cnt[g];
        }
        s_off[GEXP] = acc;
        g_num_tiles = nt;
        for (int g = 0; g <= GEXP; g++) g_offsets[g] = s_off[g];
    }
    __syncthreads();

    for (int i = t; i < B; i += blockDim.x) {
        int g = is64 ? (int)((const long long*)goal_raw)[i]
                     : ((const int*)goal_raw)[i];
        int pos = s_off[g] + atomicAdd(&s_fill[g], 1);
        g_perm[pos] = i;
    }
}

// ---------------------------------------------------------------------------
// Convert + transpose weights: W[mat][g][d][h] fp32 -> Wt hi/lo bf16 [g][h][d]
// ---------------------------------------------------------------------------
__global__ __launch_bounds__(256) void convert_w_kernel(
    const float* __restrict__ Wp0, const float* __restrict__ Wp1,
    const float* __restrict__ Wv0, const float* __restrict__ Wv1)
{
    __shared__ float tile[32][33];
    const int mat = blockIdx.z >> 4;
    const int g   = blockIdx.z & 15;
    const float* W = (mat == 0) ? Wp0 : (mat == 1) ? Wp1 : (mat == 2) ? Wv0 : Wv1;
    const float* Wg = W + (size_t)g * DDIM * DDIM;
    const int h0 = blockIdx.x * 32, d0 = blockIdx.y * 32;
    const int tx = threadIdx.x & 31, ty = threadIdx.x >> 5;

    #pragma unroll
    for (int i = ty; i < 32; i += 8)
        tile[i][tx] = Wg[(size_t)(d0 + i) * DDIM + h0 + tx];
    __syncthreads();

    __nv_bfloat16* Oh = g_Wt_hi[mat] + (size_t)g * DDIM * DDIM;
    __nv_bfloat16* Ol = g_Wt_lo[mat] + (size_t)g * DDIM * DDIM;
    #pragma unroll
    for (int i = ty; i < 32; i += 8) {
        float v = tile[tx][i];                 // W[d0+tx][h0+i]
        size_t o = (size_t)(h0 + i) * DDIM + d0 + tx;
        __nv_bfloat16 hi = __float2bfloat16(v);
        Oh[o] = hi;
        Ol[o] = __float2bfloat16(v - __bfloat162float(hi));
    }
}

__global__ void convert_f_kernel(const float* __restrict__ X, int n)
{
    for (int i = blockIdx.x * blockDim.x + threadIdx.x; i < n;
         i += gridDim.x * blockDim.x) {
        float v = X[i];
        __nv_bfloat16 hi = __float2bfloat16(v);
        g_A_hi[i] = hi;
        g_A_lo[i] = __float2bfloat16(v - __bfloat162float(hi));
    }
}

// ---------------------------------------------------------------------------
// Grouped GEMM layer via WMMA (HMMA, portable - no sm_103a-only instructions).
// CTA tile 128x128, 8 warps each 32x64, K chunks of 64 via cp.async.
// 3-term bf16 split: Ah*Bh + Ah*Bl + Al*Bh, fp32 accumulate.
// blockIdx: x = M-tile, y = N-tile (0..3), z = branch.
// ---------------------------------------------------------------------------
__global__ __launch_bounds__(256, 2)
void gemm_layer(const float* __restrict__ bias_pi, const float* __restrict__ bias_vf,
                float* __restrict__ out, int layer, int B)
{
    const int tile = blockIdx.x;
    if (tile >= g_num_tiles) return;
    const int g    = g_tile_expert[tile];
    const int row0 = g_tile_row[tile];
    int rows = g_offsets[g + 1] - row0;
    if (rows > TILEM) rows = TILEM;
    const int n0 = blockIdx.y * 128;
    const int z  = blockIdx.z;
    const int mat = z * 2 + layer;

    extern __shared__ char smem[];
    __nv_bfloat16* As_hi = (__nv_bfloat16*)(smem);
    __nv_bfloat16* As_lo = (__nv_bfloat16*)(smem + 18432);
    __nv_bfloat16* Bs_hi = (__nv_bfloat16*)(smem + 36864);
    __nv_bfloat16* Bs_lo = (__nv_bfloat16*)(smem + 55296);
    const uint32_t sA_hi = smem_u32(As_hi);
    const uint32_t sA_lo = smem_u32(As_lo);
    const uint32_t sB_hi = smem_u32(Bs_hi);
    const uint32_t sB_lo = smem_u32(Bs_lo);

    const int tid  = threadIdx.x;
    const int wid  = tid >> 5;

    const __nv_bfloat16* Ah = (layer == 0) ? g_A_hi : g_H_hi[z];
    const __nv_bfloat16* Al = (layer == 0) ? g_A_lo : g_H_lo[z];
    const __nv_bfloat16* Bh = g_Wt_hi[mat] + ((size_t)g * DDIM + n0) * DDIM;
    const __nv_bfloat16* Bl = g_Wt_lo[mat] + ((size_t)g * DDIM + n0) * DDIM;

    // loader mapping: 2 threads per row, each covers 32 of 64 k-elems
    const int r    = tid >> 1;          // 0..127
    const int half = tid & 1;           // 0 or 1
    const int kel  = half * 32;         // element offset within chunk

    int arow = -1;
    if (r < rows) arow = (layer == 0) ? g_perm[row0 + r] : (row0 + r);

    // zero A slots of invalid rows once (never overwritten afterwards)
    if (arow < 0) {
        float4 zz = make_float4(0.f, 0.f, 0.f, 0.f);
        #pragma unroll
        for (int j = 0; j < 4; j++) {
            *(float4*)((char*)As_hi + r * 144 + half * 64 + j * 16) = zz;
            *(float4*)((char*)As_lo + r * 144 + half * 64 + j * 16) = zz;
        }
    }
    __syncthreads();

    // warp tile: 32 rows x 64 cols
    const int wm0 = (wid & 3) * 32;     // warp row base within CTA tile
    const int wn0 = (wid >> 2) * 64;    // warp col base within CTA tile

    wmma::fragment<wmma::accumulator, 16, 16, 16, float> acc[2][4];
    #pragma unroll
    for (int i = 0; i < 2; i++)
        #pragma unroll
        for (int j = 0; j < 4; j++)
            wmma::fill_fragment(acc[i][j], 0.0f);

    #pragma unroll 1
    for (int s = 0; s < 8; s++) {
        const int kc = s * 64;
        // ---- load chunk (cp.async) ----
        {
            const uint32_t so = (uint32_t)(r * 144 + half * 64);
            if (arow >= 0) {
                const __nv_bfloat16* pah = Ah + (size_t)arow * DDIM + kc + kel;
                const __nv_bfloat16* pal = Al + (size_t)arow * DDIM + kc + kel;
                #pragma unroll
                for (int j = 0; j < 4; j++) {
                    cp16(sA_hi + so + j * 16, pah + j * 8);
                    cp16(sA_lo + so + j * 16, pal + j * 8);
                }
            }
            const __nv_bfloat16* pbh = Bh + (size_t)r * DDIM + kc + kel;
            const __nv_bfloat16* pbl = Bl + (size_t)r * DDIM + kc + kel;
            #pragma unroll
            for (int j = 0; j < 4; j++) {
                cp16(sB_hi + so + j * 16, pbh + j * 8);
                cp16(sB_lo + so + j * 16, pbl + j * 8);
            }
        }
        asm volatile("cp.async.commit_group;" ::: "memory");
        asm volatile("cp.async.wait_group 0;" ::: "memory");
        __syncthreads();

        // ---- compute: 4 k-steps of 16 ----
        #pragma unroll
        for (int kk = 0; kk < 4; kk++) {
            const int ko = kk * 16;
            wmma::fragment<wmma::matrix_a, 16, 16, 16, __nv_bfloat16, wmma::row_major> fa[2];
            wmma::fragment<wmma::matrix_a, 16, 16, 16, __nv_bfloat16, wmma::row_major> fal[2];
            wmma::fragment<wmma::matrix_b, 16, 16, 16, __nv_bfloat16, wmma::col_major> fb[4];

            #pragma unroll
            for (int i = 0; i < 2; i++) {
                wmma::load_matrix_sync(fa[i],  As_hi + (wm0 + i * 16) * LDA + ko, LDA);
                wmma::load_matrix_sync(fal[i], As_lo + (wm0 + i * 16) * LDA + ko, LDA);
            }
            // B is [n][k] row-major == K x N col-major
            #pragma unroll
            for (int j = 0; j < 4; j++)
                wmma::load_matrix_sync(fb[j], Bs_hi + (wn0 + j * 16) * LDA + ko, LDA);

            // Ah*Bh and Al*Bh
            #pragma unroll
            for (int i = 0; i < 2; i++)
                #pragma unroll
                for (int j = 0; j < 4; j++) {
                    wmma::mma_sync(acc[i][j], fa[i],  fb[j], acc[i][j]);
                    wmma::mma_sync(acc[i][j], fal[i], fb[j], acc[i][j]);
                }
            // Ah*Bl
            #pragma unroll
            for (int j = 0; j < 4; j++)
                wmma::load_matrix_sync(fb[j], Bs_lo + (wn0 + j * 16) * LDA + ko, LDA);
            #pragma unroll
            for (int i = 0; i < 2; i++)
                #pragma unroll
                for (int j = 0; j < 4; j++)
                    wmma::mma_sync(acc[i][j], fa[i], fb[j], acc[i][j]);
        }
        __syncthreads();   // compute done before next chunk overwrites smem
    }

    // ---- stage accumulators to smem f32 (reuse operand buffers) ----
    float* stage = (float*)smem;
    #pragma unroll
    for (int i = 0; i < 2; i++)
        #pragma unroll
        for (int j = 0; j < 4; j++)
            wmma::store_matrix_sync(stage + (wm0 + i * 16) * LDS_F32 + wn0 + j * 16,
                                    acc[i][j], LDS_F32, wmma::mem_row_major);
    __syncthreads();

    // ---- epilogue: bias + tanh ----
    const int m     = tid >> 1;          // 0..127
    const int cbase = (tid & 1) * 64;    // 0 or 64
    if (m < rows) {
        const float* bias = ((z == 0) ? bias_pi : bias_vf) + g * DDIM + n0 + cbase;
        const float* srow = stage + m * LDS_F32 + cbase;
        const int prow = row0 + m;
        if (layer == 0) {
            __nv_bfloat16* OH = g_H_hi[z] + (size_t)prow * DDIM + n0 + cbase;
            __nv_bfloat16* OL = g_H_lo[z] + (size_t)prow * DDIM + n0 + cbase;
            #pragma unroll
            for (int c = 0; c < 64; c += 2) {
                float v0 = tanhf(srow[c]     + __ldg(bias + c));
                float v1 = tanhf(srow[c + 1] + __ldg(bias + c + 1));
                __nv_bfloat16 h0 = __float2bfloat16(v0);
                __nv_bfloat16 h1 = __float2bfloat16(v1);
                __nv_bfloat16 l0 = __float2bfloat16(v0 - __bfloat162float(h0));
                __nv_bfloat16 l1 = __float2bfloat16(v1 - __bfloat162float(h1));
                *(__nv_bfloat162*)(OH + c) = __halves2bfloat162(h0, h1);
                *(__nv_bfloat162*)(OL + c) = __halves2bfloat162(l0, l1);
            }
        } else {
            int orow = g_perm[prow];
            float* OF = out + ((size_t)z * B + orow) * DDIM + n0 + cbase;
            #pragma unroll
            for (int c = 0; c < 64; c += 4) {
                float4 o;
                o.x = tanhf(srow[c]     + __ldg(bias + c));
                o.y = tanhf(srow[c + 1] + __ldg(bias + c + 1));
                o.z = tanhf(srow[c + 2] + __ldg(bias + c + 2));
                o.w = tanhf(srow[c + 3] + __ldg(bias + c + 3));
                *(float4*)(OF + c) = o;
            }
        }
    }
}

// ---------------------------------------------------------------------------
extern "C" void kernel_launch(void* const* d_in, const int* in_sizes, int n_in,
                              void* d_out, int out_size)
{
    const float* features = (const float*)d_in[0];
    const float* Wp0 = (const float*)d_in[1];
    const float* bp0 = (const float*)d_in[2];
    const float* Wp1 = (const float*)d_in[3];
    const float* bp1 = (const float*)d_in[4];
    const float* Wv0 = (const float*)d_in[5];
    const float* bv0 = (const float*)d_in[6];
    const float* Wv1 = (const float*)d_in[7];
    const float* bv1 = (const float*)d_in[8];
    const void*  goal = d_in[9];

    int B = in_sizes[0] / DDIM;
    if (B > BMAX) B = BMAX;

    cudaFuncSetAttribute(gemm_layer, cudaFuncAttributeMaxDynamicSharedMemorySize, SMEM_TOTAL);

    setup_kernel<<<1, 1024>>>(goal, B);
    convert_w_kernel<<<dim3(16, 16, 64), 256>>>(Wp0, Wp1, Wv0, Wv1);
    convert_f_kernel<<<1024, 256>>>(features, B * DDIM);

    dim3 gg(B / TILEM + GEXP, 4, 2);
    gemm_layer<<<gg, 256, SMEM_TOTAL>>>(bp0, bv0, nullptr, 0, B);
    gemm_layer<<<gg, 256, SMEM_TOTAL>>>(bp1, bv1, (float*)d_out, 1, B);
}

// round 7
// speedup vs baseline: 1.3539x; 1.0801x over previous
#include <cuda_runtime.h>
#include <cuda_bf16.h>
#include <mma.h>
#include <cstdint>

using namespace nvcuda;

#define GEXP 16
#define DDIM 512
#define BMAX 4096
#define TILEM 128
#define MAXTILES (BMAX / TILEM + GEXP)
#define KCH 32
#define LDA 40                        // bf16 elems per smem row (32 + 8 pad) = 80 B
#define STAGE_MAT 10240               // bytes per matrix per stage (128*40*2)
#define STAGE_BYTES (4 * STAGE_MAT)   // 40960
#define SMEM_TOTAL (2 * STAGE_BYTES)  // 81920 (f32 staging 128*132*4=67584 fits)
#define LDS_F32 132
#define NCHUNK (DDIM / KCH)           // 16

// ---------------- device scratch (static; no allocations allowed) ----------
__device__ int g_offsets[GEXP + 1];
__device__ int g_perm[BMAX];
__device__ int g_tile_expert[MAXTILES];
__device__ int g_tile_row[MAXTILES];
__device__ int g_num_tiles;

// transposed bf16 hi/lo weights: [mat][g][h][d], d contiguous
__device__ __nv_bfloat16 g_Wt_hi[4][GEXP * DDIM * DDIM];
__device__ __nv_bfloat16 g_Wt_lo[4][GEXP * DDIM * DDIM];
// features split (original token order)
__device__ __nv_bfloat16 g_A_hi[BMAX * DDIM];
__device__ __nv_bfloat16 g_A_lo[BMAX * DDIM];
// layer-0 hidden split, permuted token order, [branch]
__device__ __nv_bfloat16 g_H_hi[2][BMAX * DDIM];
__device__ __nv_bfloat16 g_H_lo[2][BMAX * DDIM];

// ---------------- helpers ---------------------------------------------------
__device__ __forceinline__ uint32_t smem_u32(const void* p) {
    uint32_t a;
    asm("{ .reg .u64 t; cvta.to.shared.u64 t, %1; cvt.u32.u64 %0, t; }" : "=r"(a) : "l"(p));
    return a;
}

__device__ __forceinline__ void cp16(uint32_t dst, const void* src) {
    size_t gsrc = (size_t)__cvta_generic_to_global(src);
    asm volatile("cp.async.cg.shared.global [%0], [%1], 16;" :: "r"(dst), "l"(gsrc) : "memory");
}

// ---------------------------------------------------------------------------
// Setup: dtype-detect goal, histogram, offsets, permutation, tile list.
// ---------------------------------------------------------------------------
__global__ void setup_kernel(const void* __restrict__ goal_raw, int B)
{
    __shared__ int s_cnt[GEXP];
    __shared__ int s_off[GEXP + 1];
    __shared__ int s_fill[GEXP];
    __shared__ int s_is64;

    int t = threadIdx.x;
    if (t < GEXP) { s_cnt[t] = 0; s_fill[t] = 0; }
    if (t == 0) {
        const long long* p = (const long long*)goal_raw;
        int f = 1;
        int n = (B < 32) ? B : 32;
        for (int i = 0; i < n; i++) {
            long long v = p[i];
            if (v < 0 || v >= GEXP) { f = 0; break; }
        }
        s_is64 = f;
    }
    __syncthreads();
    const int is64 = s_is64;

    for (int i = t; i < B; i += blockDim.x) {
        int g = is64 ? (int)((const long long*)goal_raw)[i]
                     : ((const int*)goal_raw)[i];
        atomicAdd(&s_cnt[g], 1);
    }
    __syncthreads();

    if (t == 0) {
        int acc = 0, nt = 0;
        for (int g = 0; g < GEXP; g++) {
            s_off[g] = acc;
            for (int r = 0; r < s_cnt[g]; r += TILEM) {
                g_tile_expert[nt] = g;
                g_tile_row[nt]    = acc + r;
                nt++;
            }
            acc += s_cnt[g];
        }
        s_off[GEXP] = acc;
        g_num_tiles = nt;
        for (int g = 0; g <= GEXP; g++) g_offsets[g] = s_off[g];
    }
    __syncthreads();

    for (int i = t; i < B; i += blockDim.x) {
        int g = is64 ? (int)((const long long*)goal_raw)[i]
                     : ((const int*)goal_raw)[i];
        int pos = s_off[g] + atomicAdd(&s_fill[g], 1);
        g_perm[pos] = i;
    }
}

// ---------------------------------------------------------------------------
// Convert + transpose weights: W[mat][g][d][h] fp32 -> Wt hi/lo bf16 [g][h][d]
// ---------------------------------------------------------------------------
__global__ __launch_bounds__(256) void convert_w_kernel(
    const float* __restrict__ Wp0, const float* __restrict__ Wp1,
    const float* __restrict__ Wv0, const float* __restrict__ Wv1)
{
    __shared__ float tile[32][33];
    const int mat = blockIdx.z >> 4;
    const int g   = blockIdx.z & 15;
    const float* W = (mat == 0) ? Wp0 : (mat == 1) ? Wp1 : (mat == 2) ? Wv0 : Wv1;
    const float* Wg = W + (size_t)g * DDIM * DDIM;
    const int h0 = blockIdx.x * 32, d0 = blockIdx.y * 32;
    const int tx = threadIdx.x & 31, ty = threadIdx.x >> 5;

    #pragma unroll
    for (int i = ty; i < 32; i += 8)
        tile[i][tx] = Wg[(size_t)(d0 + i) * DDIM + h0 + tx];
    __syncthreads();

    __nv_bfloat16* Oh = g_Wt_hi[mat] + (size_t)g * DDIM * DDIM;
    __nv_bfloat16* Ol = g_Wt_lo[mat] + (size_t)g * DDIM * DDIM;
    #pragma unroll
    for (int i = ty; i < 32; i += 8) {
        float v = tile[tx][i];                 // W[d0+tx][h0+i]
        size_t o = (size_t)(h0 + i) * DDIM + d0 + tx;
        __nv_bfloat16 hi = __float2bfloat16(v);
        Oh[o] = hi;
        Ol[o] = __float2bfloat16(v - __bfloat162float(hi));
    }
}

__global__ void convert_f_kernel(const float* __restrict__ X, int n)
{
    for (int i = blockIdx.x * blockDim.x + threadIdx.x; i < n;
         i += gridDim.x * blockDim.x) {
        float v = X[i];
        __nv_bfloat16 hi = __float2bfloat16(v);
        g_A_hi[i] = hi;
        g_A_lo[i] = __float2bfloat16(v - __bfloat162float(hi));
    }
}

// ---------------------------------------------------------------------------
// Grouped GEMM layer via WMMA (HMMA), DOUBLE-BUFFERED cp.async pipeline.
// CTA tile 128x128, 8 warps each 32x64, K chunks of 32, 2 smem stages.
// 3-term bf16 split: Ah*Bh + Ah*Bl + Al*Bh, fp32 accumulate.
// Loads fully inlined (no lambda). blockIdx: x = M-tile, y = N-tile, z = branch.
// ---------------------------------------------------------------------------
__global__ __launch_bounds__(256, 2)
void gemm_layer(const float* __restrict__ bias_pi, const float* __restrict__ bias_vf,
                float* __restrict__ out, int layer, int B)
{
    const int tile = blockIdx.x;
    if (tile >= g_num_tiles) return;
    const int g    = g_tile_expert[tile];
    const int row0 = g_tile_row[tile];
    int rows = g_offsets[g + 1] - row0;
    if (rows > TILEM) rows = TILEM;
    const int n0 = blockIdx.y * 128;
    const int z  = blockIdx.z;
    const int mat = z * 2 + layer;

    extern __shared__ char smem[];
    const uint32_t sbase = smem_u32(smem);

    const int tid = threadIdx.x;
    const int wid = tid >> 5;

    const __nv_bfloat16* Ah = (layer == 0) ? g_A_hi : g_H_hi[z];
    const __nv_bfloat16* Al = (layer == 0) ? g_A_lo : g_H_lo[z];
    const __nv_bfloat16* Bh = g_Wt_hi[mat] + ((size_t)g * DDIM + n0) * DDIM;
    const __nv_bfloat16* Bl = g_Wt_lo[mat] + ((size_t)g * DDIM + n0) * DDIM;

    // loader mapping: 2 threads per row, each covers 16 bf16 = 32 B (2x cp16)
    const int r    = tid >> 1;          // 0..127
    const int half = tid & 1;           // 0 or 1
    const int kel  = half * 16;         // element offset within chunk

    int arow = -1;
    if (r < rows) arow = (layer == 0) ? g_perm[row0 + r] : (row0 + r);

    // per-thread source pointers (advance by KCH per chunk)
    const __nv_bfloat16* pah = (arow >= 0) ? (Ah + (size_t)arow * DDIM + kel) : nullptr;
    const __nv_bfloat16* pal = (arow >= 0) ? (Al + (size_t)arow * DDIM + kel) : nullptr;
    const __nv_bfloat16* pbh = Bh + (size_t)r * DDIM + kel;
    const __nv_bfloat16* pbl = Bl + (size_t)r * DDIM + kel;
    const uint32_t soff = (uint32_t)(r * 80 + half * 32);   // dst offset within a matrix

    // zero A slots of invalid rows in BOTH stages (never overwritten by cp.async)
    if (arow < 0) {
        float4 zz = make_float4(0.f, 0.f, 0.f, 0.f);
        #pragma unroll
        for (int st = 0; st < 2; st++) {
            char* p = smem + st * STAGE_BYTES + soff;
            *(float4*)(p)                  = zz;   // Ah [0,16)
            *(float4*)(p + 16)             = zz;   // Ah [16,32)
            *(float4*)(p + STAGE_MAT)      = zz;   // Al
            *(float4*)(p + STAGE_MAT + 16) = zz;
        }
    }

    // warp tile: 32 rows x 64 cols
    const int wm0 = (wid & 3) * 32;
    const int wn0 = (wid >> 2) * 64;

    wmma::fragment<wmma::accumulator, 16, 16, 16, float> acc[2][4];
    #pragma unroll
    for (int i = 0; i < 2; i++)
        #pragma unroll
        for (int j = 0; j < 4; j++)
            wmma::fill_fragment(acc[i][j], 0.0f);

    // ---- prologue: load chunk 0 into buffer 0 ----
    {
        const uint32_t base = sbase + soff;
        if (arow >= 0) {
            cp16(base,                  pah);
            cp16(base + 16,             pah + 8);
            cp16(base + STAGE_MAT,      pal);
            cp16(base + STAGE_MAT + 16, pal + 8);
        }
        cp16(base + 2 * STAGE_MAT,      pbh);
        cp16(base + 2 * STAGE_MAT + 16, pbh + 8);
        cp16(base + 3 * STAGE_MAT,      pbl);
        cp16(base + 3 * STAGE_MAT + 16, pbl + 8);
        asm volatile("cp.async.commit_group;" ::: "memory");
    }

    #pragma unroll 1
    for (int s = 0; s < NCHUNK; s++) {
        if (s + 1 < NCHUNK) {
            // ---- issue load of chunk s+1 into the other buffer ----
            const int kc1 = (s + 1) * KCH;
            const uint32_t base = sbase + ((s + 1) & 1) * STAGE_BYTES + soff;
            if (arow >= 0) {
                cp16(base,                  pah + kc1);
                cp16(base + 16,             pah + kc1 + 8);
                cp16(base + STAGE_MAT,      pal + kc1);
                cp16(base + STAGE_MAT + 16, pal + kc1 + 8);
            }
            cp16(base + 2 * STAGE_MAT,      pbh + kc1);
            cp16(base + 2 * STAGE_MAT + 16, pbh + kc1 + 8);
            cp16(base + 3 * STAGE_MAT,      pbl + kc1);
            cp16(base + 3 * STAGE_MAT + 16, pbl + kc1 + 8);
            asm volatile("cp.async.commit_group;" ::: "memory");
            asm volatile("cp.async.wait_group 1;" ::: "memory");
        } else {
            asm volatile("cp.async.wait_group 0;" ::: "memory");
        }
        __syncthreads();   // stage s resident for all warps

        const int buf = s & 1;
        const __nv_bfloat16* As_hi = (const __nv_bfloat16*)(smem + buf * STAGE_BYTES);
        const __nv_bfloat16* As_lo = (const __nv_bfloat16*)(smem + buf * STAGE_BYTES + STAGE_MAT);
        const __nv_bfloat16* Bs_hi = (const __nv_bfloat16*)(smem + buf * STAGE_BYTES + 2 * STAGE_MAT);
        const __nv_bfloat16* Bs_lo = (const __nv_bfloat16*)(smem + buf * STAGE_BYTES + 3 * STAGE_MAT);

        #pragma unroll
        for (int kk = 0; kk < KCH / 16; kk++) {
            const int ko = kk * 16;
            wmma::fragment<wmma::matrix_a, 16, 16, 16, __nv_bfloat16, wmma::row_major> fa[2];
            wmma::fragment<wmma::matrix_a, 16, 16, 16, __nv_bfloat16, wmma::row_major> fal[2];
            wmma::fragment<wmma::matrix_b, 16, 16, 16, __nv_bfloat16, wmma::col_major> fb[4];

            #pragma unroll
            for (int i = 0; i < 2; i++) {
                wmma::load_matrix_sync(fa[i],  As_hi + (wm0 + i * 16) * LDA + ko, LDA);
                wmma::load_matrix_sync(fal[i], As_lo + (wm0 + i * 16) * LDA + ko, LDA);
            }
            #pragma unroll
            for (int j = 0; j < 4; j++)
                wmma::load_matrix_sync(fb[j], Bs_hi + (wn0 + j * 16) * LDA + ko, LDA);

            #pragma unroll
            for (int i = 0; i < 2; i++)
                #pragma unroll
                for (int j = 0; j < 4; j++) {
                    wmma::mma_sync(acc[i][j], fa[i],  fb[j], acc[i][j]);
                    wmma::mma_sync(acc[i][j], fal[i], fb[j], acc[i][j]);
                }
            #pragma unroll
            for (int j = 0; j < 4; j++)
                wmma::load_matrix_sync(fb[j], Bs_lo + (wn0 + j * 16) * LDA + ko, LDA);
            #pragma unroll
            for (int i = 0; i < 2; i++)
                #pragma unroll
                for (int j = 0; j < 4; j++)
                    wmma::mma_sync(acc[i][j], fa[i], fb[j], acc[i][j]);
        }
        __syncthreads();   // compute done before this buffer is refilled (s+2)
    }

    // ---- stage accumulators to smem f32 (reuse operand buffers) ----
    float* stage = (float*)smem;
    #pragma unroll
    for (int i = 0; i < 2; i++)
        #pragma unroll
        for (int j = 0; j < 4; j++)
            wmma::store_matrix_sync(stage + (wm0 + i * 16) * LDS_F32 + wn0 + j * 16,
                                    acc[i][j], LDS_F32, wmma::mem_row_major);
    __syncthreads();

    // ---- epilogue: bias + tanh ----
    const int m     = tid >> 1;
    const int cbase = (tid & 1) * 64;
    if (m < rows) {
        const float* bias = ((z == 0) ? bias_pi : bias_vf) + g * DDIM + n0 + cbase;
        const float* srow = stage + m * LDS_F32 + cbase;
        const int prow = row0 + m;
        if (layer == 0) {
            __nv_bfloat16* OH = g_H_hi[z] + (size_t)prow * DDIM + n0 + cbase;
            __nv_bfloat16* OL = g_H_lo[z] + (size_t)prow * DDIM + n0 + cbase;
            #pragma unroll
            for (int c = 0; c < 64; c += 2) {
                float v0 = tanhf(srow[c]     + __ldg(bias + c));
                float v1 = tanhf(srow[c + 1] + __ldg(bias + c + 1));
                __nv_bfloat16 h0 = __float2bfloat16(v0);
                __nv_bfloat16 h1 = __float2bfloat16(v1);
                __nv_bfloat16 l0 = __float2bfloat16(v0 - __bfloat162float(h0));
                __nv_bfloat16 l1 = __float2bfloat16(v1 - __bfloat162float(h1));
                *(__nv_bfloat162*)(OH + c) = __halves2bfloat162(h0, h1);
                *(__nv_bfloat162*)(OL + c) = __halves2bfloat162(l0, l1);
            }
        } else {
            int orow = g_perm[prow];
            float* OF = out + ((size_t)z * B + orow) * DDIM + n0 + cbase;
            #pragma unroll
            for (int c = 0; c < 64; c += 4) {
                float4 o;
                o.x = tanhf(srow[c]     + __ldg(bias + c));
                o.y = tanhf(srow[c + 1] + __ldg(bias + c + 1));
                o.z = tanhf(srow[c + 2] + __ldg(bias + c + 2));
                o.w = tanhf(srow[c + 3] + __ldg(bias + c + 3));
                *(float4*)(OF + c) = o;
            }
        }
    }
}

// ---------------------------------------------------------------------------
extern "C" void kernel_launch(void* const* d_in, const int* in_sizes, int n_in,
                              void* d_out, int out_size)
{
    const float* features = (const float*)d_in[0];
    const float* Wp0 = (const float*)d_in[1];
    const float* bp0 = (const float*)d_in[2];
    const float* Wp1 = (const float*)d_in[3];
    const float* bp1 = (const float*)d_in[4];
    const float* Wv0 = (const float*)d_in[5];
    const float* bv0 = (const float*)d_in[6];
    const float* Wv1 = (const float*)d_in[7];
    const float* bv1 = (const float*)d_in[8];
    const void*  goal = d_in[9];

    int B = in_sizes[0] / DDIM;
    if (B > BMAX) B = BMAX;

    cudaFuncSetAttribute(gemm_layer, cudaFuncAttributeMaxDynamicSharedMemorySize, SMEM_TOTAL);

    setup_kernel<<<1, 1024>>>(goal, B);
    convert_w_kernel<<<dim3(16, 16, 64), 256>>>(Wp0, Wp1, Wv0, Wv1);
    convert_f_kernel<<<1024, 256>>>(features, B * DDIM);

    dim3 gg(B / TILEM + GEXP, 4, 2);
    gemm_layer<<<gg, 256, SMEM_TOTAL>>>(bp0, bv0, nullptr, 0, B);
    gemm_layer<<<gg, 256, SMEM_TOTAL>>>(bp1, bv1, (float*)d_out, 1, B);
}